// round 2
// baseline (speedup 1.0000x reference)
#include <cuda_runtime.h>
#include <cuda_bf16.h>

#define N_NODES 20000
#define N_EDGES 5000
#define STEPS 50
#define EDGE_STRIDE 128   // max nodes per edge (mean ~40, Poisson tail safe)
#define NODE_STRIDE 64    // max edges per node (mean ~10, Poisson tail safe)

// ---------------- scratch (device globals: no allocation allowed) ----------
__device__ int   g_edge_cnt[N_EDGES];
__device__ int   g_node_cnt[N_NODES];
__device__ int   g_edge_nodes[N_EDGES * EDGE_STRIDE];   // nodes in each edge
__device__ int   g_node_edges[N_NODES * NODE_STRIDE];   // edges touching each node
__device__ float g_agg[N_EDGES];                        // H @ I
__device__ float g_I[N_NODES];                          // current infected fraction

// ---------------- init: zero counters, copy x -> traj[0], seed g_I ----------
__global__ void k_init(const float* __restrict__ x, float* __restrict__ out) {
    int i = blockIdx.x * blockDim.x + threadIdx.x;
    if (i < N_EDGES) g_edge_cnt[i] = 0;
    if (i < N_NODES) {
        g_node_cnt[i] = 0;
        float s  = x[i * 3 + 0];
        float in = x[i * 3 + 1];
        float r  = x[i * 3 + 2];
        out[i * 3 + 0] = s;
        out[i * 3 + 1] = in;
        out[i * 3 + 2] = r;
        g_I[i] = in;
    }
}

// ---------------- build sparse structure from dense H (400 MB scan) --------
// H is row-major [N_EDGES][N_NODES]; N_NODES % 4 == 0 so float4 never crosses
// a row boundary.
__global__ void k_build(const float4* __restrict__ H4) {
    const long total4 = (long)N_EDGES * N_NODES / 4;  // 25M
    long stride = (long)gridDim.x * blockDim.x;
    for (long i = (long)blockIdx.x * blockDim.x + threadIdx.x; i < total4; i += stride) {
        float4 v = H4[i];
        if (v.x != 0.f || v.y != 0.f || v.z != 0.f || v.w != 0.f) {
            long base = i * 4;
            float vals[4] = {v.x, v.y, v.z, v.w};
            #pragma unroll
            for (int k = 0; k < 4; k++) {
                if (vals[k] != 0.f) {
                    long idx = base + k;
                    int e = (int)(idx / N_NODES);
                    int n = (int)(idx - (long)e * N_NODES);
                    int p = atomicAdd(&g_edge_cnt[e], 1);
                    if (p < EDGE_STRIDE) g_edge_nodes[e * EDGE_STRIDE + p] = n;
                    int q = atomicAdd(&g_node_cnt[n], 1);
                    if (q < NODE_STRIDE) g_node_edges[n * NODE_STRIDE + q] = e;
                }
            }
        }
    }
}

// ---------------- phase A: agg[e] = sum_{n in e} I[n]  (warp per edge) -----
__global__ void k_agg() {
    int gtid = blockIdx.x * blockDim.x + threadIdx.x;
    int e    = gtid >> 5;
    int lane = threadIdx.x & 31;
    if (e >= N_EDGES) return;
    int cnt = g_edge_cnt[e];
    cnt = (cnt < EDGE_STRIDE) ? cnt : EDGE_STRIDE;
    float s = 0.f;
    for (int j = lane; j < cnt; j += 32)
        s += g_I[g_edge_nodes[e * EDGE_STRIDE + j]];
    #pragma unroll
    for (int o = 16; o; o >>= 1) s += __shfl_xor_sync(0xffffffffu, s, o);
    if (lane == 0) g_agg[e] = s;
}

// ---------------- phase B + SIR update (thread per node) -------------------
__global__ void k_update(const float* __restrict__ beta,
                         const float* __restrict__ gamma,
                         float* __restrict__ out, int t) {
    int n = blockIdx.x * blockDim.x + threadIdx.x;
    if (n >= N_NODES) return;
    int cnt = g_node_cnt[n];
    cnt = (cnt < NODE_STRIDE) ? cnt : NODE_STRIDE;
    float back = 0.f;
    #pragma unroll 4
    for (int j = 0; j < cnt; j++)
        back += g_agg[g_node_edges[n * NODE_STRIDE + j]];

    const float* prev = out + (long)(t - 1) * N_NODES * 3 + n * 3;
    float S = prev[0], I = prev[1], R = prev[2];

    float nc = beta[n] * S * back;   // new cases
    float nr = gamma[n] * I;         // new recoveries

    float s0 = fmaxf(S - nc,        0.f);
    float s1 = fmaxf(I + nc - nr,   0.f);
    float s2 = fmaxf(R + nr,        0.f);
    float inv = 1.f / (s0 + s1 + s2);
    s0 *= inv; s1 *= inv; s2 *= inv;

    float* cur = out + (long)t * N_NODES * 3 + n * 3;
    cur[0] = s0; cur[1] = s1; cur[2] = s2;
    g_I[n] = s1;
}

// ---------------- launcher --------------------------------------------------
extern "C" void kernel_launch(void* const* d_in, const int* in_sizes, int n_in,
                              void* d_out, int out_size) {
    const float*  x     = (const float*) d_in[0];
    const float4* H4    = (const float4*)d_in[1];
    const float*  beta  = (const float*) d_in[2];
    const float*  gamma = (const float*) d_in[3];
    float*        out   = (float*)d_out;

    // init + traj[0]
    k_init<<<(N_NODES + 255) / 256, 256>>>(x, out);

    // sparse structure rebuild (HBM-bound 400 MB scan)
    k_build<<<4096, 256>>>(H4);

    // 49 time steps, 2 kernels each
    for (int t = 1; t < STEPS; t++) {
        k_agg<<<(N_EDGES * 32 + 255) / 256, 256>>>();
        k_update<<<(N_NODES + 255) / 256, 256>>>(beta, gamma, out, t);
    }
}